// round 12
// baseline (speedup 1.0000x reference)
#include <cuda_runtime.h>
#include <cuda_bf16.h>
#include <cstdint>
#include <cstddef>

#define B_ 4
#define L_ 2048
#define E_ 512
#define H_ 8
#define DK_ 64
#define DV_ 64
#define GP 72          // smem pitch (bf16), 144B == 16 mod 128 -> LDSM conflict-free
#define PV 136         // smem pitch (bf16), 272B == 16 mod 128 -> LDSM conflict-free

typedef __nv_bfloat16 bf16;
typedef __nv_bfloat162 bf162;

// ---- scratch (device globals; no allocations allowed) ----
__device__ float g_vh[B_ * L_ * E_];
__device__ float g_fc[B_ * L_ * E_];
__device__ bf16 g_qhi[B_ * L_ * E_];
__device__ bf16 g_qlo[B_ * L_ * E_];
__device__ bf16 g_khi[B_ * L_ * E_];
__device__ bf16 g_klo[B_ * L_ * E_];
__device__ bf16 g_ihi[3 * B_ * L_ * E_];
__device__ bf16 g_ilo[3 * B_ * L_ * E_];
__device__ bf16 g_whi[4 * E_ * E_];
__device__ bf16 g_wlo[4 * E_ * E_];
__device__ bf16 g_ctxhi[B_ * L_ * E_];
__device__ bf16 g_ctxlo[B_ * L_ * E_];
__device__ bf16 g_vhiT[B_ * H_ * DV_ * L_];   // [z][n(64)][k(2048)]
__device__ bf16 g_vloT[B_ * H_ * DV_ * L_];
__device__ unsigned int g_mask32[B_ * L_ * L_ / 32];  // bit-packed mask

// ============================================================================
__device__ __forceinline__ void mma16816(float* c, uint32_t a0, uint32_t a1,
                                         uint32_t a2, uint32_t a3,
                                         uint32_t b0, uint32_t b1) {
    asm volatile(
        "mma.sync.aligned.m16n8k16.row.col.f32.bf16.bf16.f32 "
        "{%0,%1,%2,%3}, {%4,%5,%6,%7}, {%8,%9}, {%0,%1,%2,%3};"
        : "+f"(c[0]), "+f"(c[1]), "+f"(c[2]), "+f"(c[3])
        : "r"(a0), "r"(a1), "r"(a2), "r"(a3), "r"(b0), "r"(b1));
}

#define LDSM_X4(r0, r1, r2, r3, addr) \
    asm volatile("ldmatrix.sync.aligned.m8n8.x4.shared.b16 {%0,%1,%2,%3}, [%4];" \
        : "=r"(r0), "=r"(r1), "=r"(r2), "=r"(r3) : "r"(addr))

__device__ __forceinline__ uint32_t smem_u32(const void* p) {
    uint32_t a;
    asm("{ .reg .u64 t; cvta.to.shared.u64 t, %1; cvt.u32.u64 %0, t; }"
        : "=r"(a) : "l"(p));
    return a;
}

__device__ __forceinline__ void split2(float f, bf16& hi, bf16& lo) {
    hi = __float2bfloat16_rn(f);
    lo = __float2bfloat16_rn(f - __bfloat162float(hi));
}

__device__ __forceinline__ uint32_t packbf2(bf16 x, bf16 y) {
    bf162 t; t.x = x; t.y = y;
    return *(uint32_t*)&t;
}

// Per-thread LDSM byte offsets.
// A (16x16 frag at row block ar0): row = ar0 + (lane&15), colofs = (lane>>1)&8
// B (two n8-blocks at nbase): row = nbase + (lane&7) + ((lane>>1)&8), colofs = lane&8
__device__ __forceinline__ uint32_t a_ldsm_off(int lane, int ar0, int pitch) {
    return (uint32_t)(((ar0 + (lane & 15)) * pitch + ((lane >> 1) & 8)) * 2);
}
__device__ __forceinline__ uint32_t b_ldsm_off(int lane, int pitch) {
    return (uint32_t)((((lane & 7) + ((lane >> 1) & 8)) * pitch + (lane & 8)) * 2);
}

// ============================================================================
// Fused attention, two-pass recompute + register-reuse AV + LDSM fragments.
// CTA = 128 q-rows of one z = h*B + b. 256 threads, 2 CTAs/SM.
// ============================================================================
__global__ __launch_bounds__(256, 2) void attn_fused_kernel(
    const bf16* __restrict__ qhi, const bf16* __restrict__ qlo,
    const bf16* __restrict__ khi, const bf16* __restrict__ klo,
    const bf16* __restrict__ vhiT, const bf16* __restrict__ vloT,
    const unsigned int* __restrict__ m32,
    float* __restrict__ attn,
    bf16* __restrict__ ctxhi, bf16* __restrict__ ctxlo)
{
    extern __shared__ __align__(16) char smem[];
    bf16* sQh = (bf16*)smem;                  // 128 x GP
    bf16* sQl = sQh + 128 * GP;
    bf16* sKh = sQl + 128 * GP;               // 128 x GP
    bf16* sKl = sKh + 128 * GP;
    bf16* sVh = sKl + 128 * GP;               // 64 x PV
    bf16* sVl = sVh + 64 * PV;
    float* sinv = (float*)(sVl + 64 * PV);    // 128

    int tid = threadIdx.x, lane = tid & 31, w = tid >> 5;
    int row0 = blockIdx.x * 128;
    int z = blockIdx.y, h = z / B_, b = z % B_;

    // ---- Q tile (persistent across both passes) ----
    {
        int r = tid >> 1, half = tid & 1;
        size_t qo = ((size_t)(b * L_ + row0 + r) * E_) + h * DK_ + half * 32;
        const uint4* gqh = (const uint4*)(qhi + qo);
        const uint4* gql = (const uint4*)(qlo + qo);
        uint4* dqh = (uint4*)(sQh + r * GP + half * 32);
        uint4* dql = (uint4*)(sQl + r * GP + half * 32);
#pragma unroll
        for (int i = 0; i < 4; i++) { dqh[i] = gqh[i]; dql[i] = gql[i]; }
    }

    int lr0 = w * 16 + (lane >> 2);
    int r0g = row0 + lr0;

    uint32_t uQh = smem_u32(sQh), uQl = smem_u32(sQl);
    uint32_t uKh = smem_u32(sKh), uKl = smem_u32(sKl);
    uint32_t uVh = smem_u32(sVh), uVl = smem_u32(sVl);
    uint32_t aoff = a_ldsm_off(lane, w * 16, GP);
    uint32_t boffK = b_ldsm_off(lane, GP);
    uint32_t boffV = b_ldsm_off(lane, PV);

    const size_t mb = (size_t)b * L_ * L_;
    const unsigned int* M0 = m32 + ((mb + (size_t)r0g * L_) >> 5);
    const unsigned int* M1 = m32 + ((mb + (size_t)(r0g + 8) * L_) >> 5);
    float* Az = attn + (size_t)z * L_ * L_;

    float rs0 = 0.f, rs1 = 0.f;

    // ================= PASS A: rowsums only =================
    for (int kt = 0; kt < 16; kt++) {
        int k0 = kt * 128;
        __syncthreads();
        {   // K tile: 128 keys x 64 dk
            int r = tid >> 1, half = tid & 1;
            size_t ko = ((size_t)(b * L_ + k0 + r) * E_) + h * DK_ + half * 32;
            const uint4* gkh = (const uint4*)(khi + ko);
            const uint4* gkl = (const uint4*)(klo + ko);
            uint4* dkh = (uint4*)(sKh + r * GP + half * 32);
            uint4* dkl = (uint4*)(sKl + r * GP + half * 32);
#pragma unroll
            for (int i = 0; i < 4; i++) { dkh[i] = gkh[i]; dkl[i] = gkl[i]; }
        }
        __syncthreads();

        float acc[16][4];
#pragma unroll
        for (int nb = 0; nb < 16; nb++)
#pragma unroll
            for (int j = 0; j < 4; j++) acc[nb][j] = 0.f;
#pragma unroll
        for (int pass = 0; pass < 3; pass++) {
            uint32_t aB = ((pass == 2) ? uQl : uQh) + aoff;
            uint32_t bB = ((pass == 1) ? uKl : uKh) + boffK;
#pragma unroll
            for (int ks = 0; ks < 4; ks++) {
                uint32_t a0, a1, a2, a3;
                LDSM_X4(a0, a1, a2, a3, aB + ks * 32);
#pragma unroll
                for (int j = 0; j < 8; j++) {
                    uint32_t b0, b1, b2, b3;
                    LDSM_X4(b0, b1, b2, b3, bB + j * (16 * GP * 2) + ks * 32);
                    mma16816(acc[2 * j],     a0, a1, a2, a3, b0, b1);
                    mma16816(acc[2 * j + 1], a0, a1, a2, a3, b2, b3);
                }
            }
        }

        int wb = k0 >> 5;
        unsigned int mw0[4] = {M0[wb], M0[wb + 1], M0[wb + 2], M0[wb + 3]};
        unsigned int mw1[4] = {M1[wb], M1[wb + 1], M1[wb + 2], M1[wb + 3]};
#pragma unroll
        for (int nb = 0; nb < 16; nb++) {
            int cl = nb * 8 + (lane & 3) * 2;
            unsigned int b0m = (mw0[cl >> 5] >> (cl & 31)) & 3u;
            unsigned int b1m = (mw1[cl >> 5] >> (cl & 31)) & 3u;
            rs0 += ((b0m & 1u) ? 0.f : __expf(acc[nb][0] * 0.125f))
                 + ((b0m & 2u) ? 0.f : __expf(acc[nb][1] * 0.125f));
            rs1 += ((b1m & 1u) ? 0.f : __expf(acc[nb][2] * 0.125f))
                 + ((b1m & 2u) ? 0.f : __expf(acc[nb][3] * 0.125f));
        }
    }

    // rowsums -> sinv
    rs0 += __shfl_xor_sync(0xffffffffu, rs0, 1);
    rs0 += __shfl_xor_sync(0xffffffffu, rs0, 2);
    rs1 += __shfl_xor_sync(0xffffffffu, rs1, 1);
    rs1 += __shfl_xor_sync(0xffffffffu, rs1, 2);
    if ((lane & 3) == 0) {
        sinv[lr0] = 1.0f / rs0;
        sinv[lr0 + 8] = 1.0f / rs1;
    }
    __syncthreads();
    float inv0 = sinv[lr0], inv1 = sinv[lr0 + 8];

    // ================= PASS B: normalize + write attn + AV =================
    float accv[8][4];
#pragma unroll
    for (int nb = 0; nb < 8; nb++)
#pragma unroll
        for (int j = 0; j < 4; j++) accv[nb][j] = 0.f;

    for (int kt = 0; kt < 16; kt++) {
        int k0 = kt * 128;
        __syncthreads();
        {   // K tile
            int r = tid >> 1, half = tid & 1;
            size_t ko = ((size_t)(b * L_ + k0 + r) * E_) + h * DK_ + half * 32;
            const uint4* gkh = (const uint4*)(khi + ko);
            const uint4* gkl = (const uint4*)(klo + ko);
            uint4* dkh = (uint4*)(sKh + r * GP + half * 32);
            uint4* dkl = (uint4*)(sKl + r * GP + half * 32);
#pragma unroll
            for (int i = 0; i < 4; i++) { dkh[i] = gkh[i]; dkl[i] = gkl[i]; }
        }
        {   // V^T tile: 64 dv x 128 keys
            int n = tid >> 2, part = tid & 3;
            const uint4* gh = (const uint4*)(vhiT + ((size_t)z * DV_ + n) * L_ + k0 + part * 32);
            const uint4* gl = (const uint4*)(vloT + ((size_t)z * DV_ + n) * L_ + k0 + part * 32);
            uint4* dh = (uint4*)(sVh + n * PV + part * 32);
            uint4* dl = (uint4*)(sVl + n * PV + part * 32);
#pragma unroll
            for (int i = 0; i < 4; i++) { dh[i] = gh[i]; dl[i] = gl[i]; }
        }
        __syncthreads();

        float acc[16][4];
#pragma unroll
        for (int nb = 0; nb < 16; nb++)
#pragma unroll
            for (int j = 0; j < 4; j++) acc[nb][j] = 0.f;
#pragma unroll
        for (int pass = 0; pass < 3; pass++) {
            uint32_t aB = ((pass == 2) ? uQl : uQh) + aoff;
            uint32_t bB = ((pass == 1) ? uKl : uKh) + boffK;
#pragma unroll
            for (int ks = 0; ks < 4; ks++) {
                uint32_t a0, a1, a2, a3;
                LDSM_X4(a0, a1, a2, a3, aB + ks * 32);
#pragma unroll
                for (int j = 0; j < 8; j++) {
                    uint32_t b0, b1, b2, b3;
                    LDSM_X4(b0, b1, b2, b3, bB + j * (16 * GP * 2) + ks * 32);
                    mma16816(acc[2 * j],     a0, a1, a2, a3, b0, b1);
                    mma16816(acc[2 * j + 1], a0, a1, a2, a3, b2, b3);
                }
            }
        }

        // mask + exp + normalize in registers; write final attn once
        int wb = k0 >> 5;
        unsigned int mw0[4] = {M0[wb], M0[wb + 1], M0[wb + 2], M0[wb + 3]};
        unsigned int mw1[4] = {M1[wb], M1[wb + 1], M1[wb + 2], M1[wb + 3]};
#pragma unroll
        for (int nb = 0; nb < 16; nb++) {
            int cl = nb * 8 + (lane & 3) * 2;
            int cg = k0 + cl;
            unsigned int b0m = (mw0[cl >> 5] >> (cl & 31)) & 3u;
            unsigned int b1m = (mw1[cl >> 5] >> (cl & 31)) & 3u;
            float p00 = (b0m & 1u) ? 0.f : __expf(acc[nb][0] * 0.125f) * inv0;
            float p01 = (b0m & 2u) ? 0.f : __expf(acc[nb][1] * 0.125f) * inv0;
            float p10 = (b1m & 1u) ? 0.f : __expf(acc[nb][2] * 0.125f) * inv1;
            float p11 = (b1m & 2u) ? 0.f : __expf(acc[nb][3] * 0.125f) * inv1;
            __stcs((float2*)(Az + (size_t)r0g * L_ + cg), make_float2(p00, p01));
            __stcs((float2*)(Az + (size_t)(r0g + 8) * L_ + cg), make_float2(p10, p11));
            acc[nb][0] = p00; acc[nb][1] = p01;
            acc[nb][2] = p10; acc[nb][3] = p11;
        }

        // AV with P as register A-fragments (C-fragment == A-fragment layout)
#pragma unroll
        for (int ks = 0; ks < 8; ks++) {
            int n0 = 2 * ks, n1 = n0 + 1;
            bf16 h00, l00, h01, l01, h10, l10, h11, l11;
            split2(acc[n0][0], h00, l00); split2(acc[n0][1], h01, l01);
            split2(acc[n0][2], h10, l10); split2(acc[n0][3], h11, l11);
            uint32_t ah0 = packbf2(h00, h01), al0 = packbf2(l00, l01);
            uint32_t ah1 = packbf2(h10, h11), al1 = packbf2(l10, l11);
            split2(acc[n1][0], h00, l00); split2(acc[n1][1], h01, l01);
            split2(acc[n1][2], h10, l10); split2(acc[n1][3], h11, l11);
            uint32_t ah2 = packbf2(h00, h01), al2 = packbf2(l00, l01);
            uint32_t ah3 = packbf2(h10, h11), al3 = packbf2(l10, l11);
#pragma unroll
            for (int j = 0; j < 4; j++) {
                uint32_t bh0, bh1, bh2, bh3, bl0, bl1, bl2, bl3;
                LDSM_X4(bh0, bh1, bh2, bh3, uVh + boffV + j * (16 * PV * 2) + ks * 32);
                LDSM_X4(bl0, bl1, bl2, bl3, uVl + boffV + j * (16 * PV * 2) + ks * 32);
                mma16816(accv[2 * j], ah0, ah1, ah2, ah3, bh0, bh1);
                mma16816(accv[2 * j], ah0, ah1, ah2, ah3, bl0, bl1);
                mma16816(accv[2 * j], al0, al1, al2, al3, bh0, bh1);
                mma16816(accv[2 * j + 1], ah0, ah1, ah2, ah3, bh2, bh3);
                mma16816(accv[2 * j + 1], ah0, ah1, ah2, ah3, bl2, bl3);
                mma16816(accv[2 * j + 1], al0, al1, al2, al3, bh2, bh3);
            }
        }
    }

    // ---- ctx epilogue (already normalized) ----
#pragma unroll
    for (int nb = 0; nb < 8; nb++) {
        int cg = nb * 8 + (lane & 3) * 2;
        size_t o0 = ((size_t)(b * L_ + r0g)) * E_ + h * DV_ + cg;
        size_t o1 = ((size_t)(b * L_ + r0g + 8)) * E_ + h * DV_ + cg;
        bf162 h2, l2;
        split2(accv[nb][0], h2.x, l2.x); split2(accv[nb][1], h2.y, l2.y);
        *(bf162*)(ctxhi + o0) = h2;
        *(bf162*)(ctxlo + o0) = l2;
        split2(accv[nb][2], h2.x, l2.x); split2(accv[nb][3], h2.y, l2.y);
        *(bf162*)(ctxhi + o1) = h2;
        *(bf162*)(ctxlo + o1) = l2;
    }
}
// Q(36864) + K(36864) + V(34816) + sinv(512)
#define AF_SMEM_BYTES (36864 + 36864 + 34816 + 512)

// ============================================================================
// Generic HMMA NT GEMM body with LDSM fragments: C = A @ B^T + bias
// ============================================================================
__device__ __forceinline__ void hmma_nt_body(
    const bf16* __restrict__ Ahi, const bf16* __restrict__ Alo,
    const bf16* __restrict__ Bhi, const bf16* __restrict__ Blo,
    const float* __restrict__ bias,
    float* __restrict__ Cf, bf16* __restrict__ Chi, bf16* __restrict__ Clo,
    int K, int ldc)
{
    extern __shared__ __align__(16) char smem[];
    bf16* sAh = (bf16*)smem;
    bf16* sAl = sAh + 128 * GP;
    bf16* sBh = sAl + 128 * GP;
    bf16* sBl = sBh + 128 * GP;

    int tid = threadIdx.x, lane = tid & 31, w = tid >> 5;
    int row0 = blockIdx.y * 128, col0 = blockIdx.x * 128;

    float acc[16][4];
#pragma unroll
    for (int nb = 0; nb < 16; nb++)
#pragma unroll
        for (int j = 0; j < 4; j++) acc[nb][j] = 0.f;

    int r = tid >> 1, half = tid & 1;
    const bf16* gAh = Ahi + (size_t)(row0 + r) * K + half * 32;
    const bf16* gAl = Alo + (size_t)(row0 + r) * K + half * 32;
    const bf16* gBh = Bhi + (size_t)(col0 + r) * K + half * 32;
    const bf16* gBl = Blo + (size_t)(col0 + r) * K + half * 32;
    bf16* dAh = sAh + r * GP + half * 32;
    bf16* dAl = sAl + r * GP + half * 32;
    bf16* dBh = sBh + r * GP + half * 32;
    bf16* dBl = sBl + r * GP + half * 32;

    uint32_t uAh = smem_u32(sAh), uAl = smem_u32(sAl);
    uint32_t uBh = smem_u32(sBh), uBl = smem_u32(sBl);
    uint32_t aoff = a_ldsm_off(lane, w * 16, GP);
    uint32_t boff = b_ldsm_off(lane, GP);

    for (int k0 = 0; k0 < K; k0 += 64) {
        __syncthreads();
        const uint4* a4h = (const uint4*)(gAh + k0);
        const uint4* a4l = (const uint4*)(gAl + k0);
        const uint4* b4h = (const uint4*)(gBh + k0);
        const uint4* b4l = (const uint4*)(gBl + k0);
#pragma unroll
        for (int i = 0; i < 4; i++) {
            ((uint4*)dAh)[i] = a4h[i];
            ((uint4*)dAl)[i] = a4l[i];
            ((uint4*)dBh)[i] = b4h[i];
            ((uint4*)dBl)[i] = b4l[i];
        }
        __syncthreads();
#pragma unroll
        for (int pass = 0; pass < 3; pass++) {
            uint32_t aB = ((pass == 2) ? uAl : uAh) + aoff;
            uint32_t bB = ((pass == 1) ? uBl : uBh) + boff;
#pragma unroll
            for (int ks = 0; ks < 4; ks++) {
                uint32_t a0, a1, a2, a3;
                LDSM_X4(a0, a1, a2, a3, aB + ks * 32);
#pragma unroll
                for (int j = 0; j < 8; j++) {
                    uint32_t b0, b1, b2, b3;
                    LDSM_X4(b0, b1, b2, b3, bB + j * (16 * GP * 2) + ks * 32);
                    mma16816(acc[2 * j],     a0, a1, a2, a3, b0, b1);
                    mma16816(acc[2 * j + 1], a0, a1, a2, a3, b2, b3);
                }
            }
        }
    }

    int r0g = row0 + w * 16 + (lane >> 2);
#pragma unroll
    for (int nb = 0; nb < 16; nb++) {
        int cg = col0 + nb * 8 + (lane & 3) * 2;
        float f00 = acc[nb][0] + bias[cg];
        float f01 = acc[nb][1] + bias[cg + 1];
        float f10 = acc[nb][2] + bias[cg];
        float f11 = acc[nb][3] + bias[cg + 1];
        if (Cf) {
            *(float2*)(Cf + (size_t)r0g * ldc + cg) = make_float2(f00, f01);
            *(float2*)(Cf + (size_t)(r0g + 8) * ldc + cg) = make_float2(f10, f11);
        }
        if (Chi) {
            bf162 h2, l2;
            split2(f00, h2.x, l2.x); split2(f01, h2.y, l2.y);
            *(bf162*)(Chi + (size_t)r0g * ldc + cg) = h2;
            *(bf162*)(Clo + (size_t)r0g * ldc + cg) = l2;
            split2(f10, h2.x, l2.x); split2(f11, h2.y, l2.y);
            *(bf162*)(Chi + (size_t)(r0g + 8) * ldc + cg) = h2;
            *(bf162*)(Clo + (size_t)(r0g + 8) * ldc + cg) = l2;
        }
    }
}
#define HMMA_SMEM (4 * 128 * GP * 2)

__global__ __launch_bounds__(256, 2) void qkv_hmma_kernel(
    const bf16* __restrict__ ihi, const bf16* __restrict__ ilo,
    const bf16* __restrict__ whi, const bf16* __restrict__ wlo,
    const float* __restrict__ bq, const float* __restrict__ bk,
    const float* __restrict__ bv,
    bf16* __restrict__ qhi, bf16* __restrict__ qlo,
    bf16* __restrict__ khi, bf16* __restrict__ klo,
    float* __restrict__ vh)
{
    int zz = blockIdx.z;
    const bf16* Ahi = ihi + (size_t)zz * (B_ * L_ * E_);
    const bf16* Alo = ilo + (size_t)zz * (B_ * L_ * E_);
    const bf16* Bhi = whi + (size_t)zz * (E_ * E_);
    const bf16* Blo = wlo + (size_t)zz * (E_ * E_);
    const float* bias = (zz == 0) ? bq : (zz == 1) ? bk : bv;
    float* Cf = (zz == 2) ? vh : nullptr;
    bf16* Chi = (zz == 0) ? qhi : (zz == 1) ? khi : nullptr;
    bf16* Clo = (zz == 0) ? qlo : (zz == 1) ? klo : nullptr;
    hmma_nt_body(Ahi, Alo, Bhi, Blo, bias, Cf, Chi, Clo, E_, E_);
}

__global__ __launch_bounds__(256, 2) void fc_hmma_kernel(
    const bf16* __restrict__ ctxhi, const bf16* __restrict__ ctxlo,
    const bf16* __restrict__ whi, const bf16* __restrict__ wlo,
    const float* __restrict__ bfc, float* __restrict__ fc)
{
    hmma_nt_body(ctxhi, ctxlo, whi + 3 * (E_ * E_), wlo + 3 * (E_ * E_),
                 bfc, fc, nullptr, nullptr, E_, E_);
}

// ============================================================================
// Input / weight splits
// ============================================================================
__global__ void split_in_kernel(const float* __restrict__ q,
                                const float* __restrict__ k,
                                const float* __restrict__ v,
                                bf16* __restrict__ ihi, bf16* __restrict__ ilo)
{
    int which = blockIdx.y;
    const float* src = (which == 0) ? q : (which == 1) ? k : v;
    bf16* hi = ihi + (size_t)which * (B_ * L_ * E_);
    bf16* lo = ilo + (size_t)which * (B_ * L_ * E_);
    size_t i = ((size_t)blockIdx.x * 256 + threadIdx.x) * 4;
    float4 a = *(const float4*)(src + i);
#pragma unroll
    for (int j = 0; j < 4; j++) {
        bf16 h, l;
        split2(((const float*)&a)[j], h, l);
        hi[i + j] = h; lo[i + j] = l;
    }
}

__global__ void split_w_kernel(const float* __restrict__ Wq,
                               const float* __restrict__ Wk,
                               const float* __restrict__ Wv,
                               const float* __restrict__ Wfc,
                               bf16* __restrict__ whi, bf16* __restrict__ wlo)
{
    int which = blockIdx.y;
    const float* src = (which == 0) ? Wq : (which == 1) ? Wk
                     : (which == 2) ? Wv : Wfc;
    bf16* hi = whi + (size_t)which * (E_ * E_);
    bf16* lo = wlo + (size_t)which * (E_ * E_);
    size_t i = ((size_t)blockIdx.x * 256 + threadIdx.x) * 4;
    float4 a = *(const float4*)(src + i);
#pragma unroll
    for (int j = 0; j < 4; j++) {
        bf16 h, l;
        split2(((const float*)&a)[j], h, l);
        hi[i + j] = h; lo[i + j] = l;
    }
}

// ============================================================================
// V transpose + split
// ============================================================================
__global__ void vT_kernel(const float* __restrict__ vh,
                          bf16* __restrict__ vhiT, bf16* __restrict__ vloT)
{
    __shared__ float s[64][65];
    int z = blockIdx.x;
    int h = z / B_, b = z % B_;
    int k0 = blockIdx.y * 64;
    int tid = threadIdx.x;
#pragma unroll
    for (int i = 0; i < 16; i++) {
        int idx = tid + i * 256;
        int kk = idx >> 6, n = idx & 63;
        s[kk][n] = vh[((size_t)(b * L_ + k0 + kk)) * E_ + h * DV_ + n];
    }
    __syncthreads();
#pragma unroll
    for (int i = 0; i < 16; i++) {
        int idx = tid + i * 256;
        int n = idx >> 6, kk = idx & 63;
        bf16 hi, lo;
        split2(s[kk][n], hi, lo);
        size_t o = ((size_t)z * DV_ + n) * L_ + k0 + kk;
        vhiT[o] = hi; vloT[o] = lo;
    }
}

// ============================================================================
// Mask -> bit-packed uint32 (auto-detect int32 vs uint8 serialization).
// ============================================================================
__global__ void mask_pack_kernel(const void* __restrict__ mask,
                                 unsigned int* __restrict__ m32)
{
    __shared__ int s_byte;
    if (threadIdx.x == 0) {
        const unsigned int* mi = (const unsigned int*)mask;
        int bm = 0;
#pragma unroll 8
        for (int i = 0; i < 64; i++) if (mi[i] > 1u) bm = 1;
        s_byte = bm;
    }
    __syncthreads();
    size_t widx = (size_t)blockIdx.x * 256 + threadIdx.x;
    unsigned int w = 0;
    if (s_byte) {
        const unsigned int* p = (const unsigned int*)mask + widx * 8; // 32 bytes
#pragma unroll
        for (int j = 0; j < 8; j++) {
            unsigned int v = p[j];
            if (v & 0x000000FFu) w |= 1u << (j * 4 + 0);
            if (v & 0x0000FF00u) w |= 1u << (j * 4 + 1);
            if (v & 0x00FF0000u) w |= 1u << (j * 4 + 2);
            if (v & 0xFF000000u) w |= 1u << (j * 4 + 3);
        }
    } else {
        const int4* p = (const int4*)mask + widx * 8;                 // 32 ints
#pragma unroll
        for (int j = 0; j < 8; j++) {
            int4 v = p[j];
            if (v.x) w |= 1u << (j * 4 + 0);
            if (v.y) w |= 1u << (j * 4 + 1);
            if (v.z) w |= 1u << (j * 4 + 2);
            if (v.w) w |= 1u << (j * 4 + 3);
        }
    }
    m32[widx] = w;
}

// ============================================================================
// Residual add + LayerNorm
// ============================================================================
__global__ void ln_kernel(const float* __restrict__ fc,
                          const float* __restrict__ resid,
                          const float* __restrict__ gamma,
                          const float* __restrict__ beta,
                          float* __restrict__ out)
{
    size_t base = (size_t)blockIdx.x * E_;
    int tid = threadIdx.x;
    float x0 = fc[base + tid] + resid[base + tid];
    float x1 = fc[base + tid + 256] + resid[base + tid + 256];
    float s = x0 + x1;
    float ss = x0 * x0 + x1 * x1;

    __shared__ float rs[8], rss[8];
#pragma unroll
    for (int o = 16; o; o >>= 1) {
        s  += __shfl_xor_sync(0xffffffffu, s, o);
        ss += __shfl_xor_sync(0xffffffffu, ss, o);
    }
    if ((tid & 31) == 0) { rs[tid >> 5] = s; rss[tid >> 5] = ss; }
    __syncthreads();
    s = 0.f; ss = 0.f;
#pragma unroll
    for (int i = 0; i < 8; i++) { s += rs[i]; ss += rss[i]; }

    float mu = s * (1.0f / E_);
    float var = ss * (1.0f / E_) - mu * mu;
    float rstd = rsqrtf(var + 1e-5f);
    out[base + tid]       = (x0 - mu) * rstd * gamma[tid] + beta[tid];
    out[base + tid + 256] = (x1 - mu) * rstd * gamma[tid + 256] + beta[tid + 256];
}

// ============================================================================
extern "C" void kernel_launch(void* const* d_in, const int* in_sizes, int n_in,
                              void* d_out, int out_size)
{
    const float* q    = (const float*)d_in[0];
    const float* k    = (const float*)d_in[1];
    const float* v    = (const float*)d_in[2];
    const void*  mask = (const void*)d_in[3];
    const float* Wq   = (const float*)d_in[4];
    const float* bq   = (const float*)d_in[5];
    const float* Wk   = (const float*)d_in[6];
    const float* bk   = (const float*)d_in[7];
    const float* Wv   = (const float*)d_in[8];
    const float* bv   = (const float*)d_in[9];
    const float* Wfc  = (const float*)d_in[10];
    const float* bfc  = (const float*)d_in[11];
    const float* gamma = (const float*)d_in[12];
    const float* beta  = (const float*)d_in[13];

    float* out  = (float*)d_out;
    float* attn = out + (size_t)B_ * L_ * E_;

    float *vh, *fc;
    bf16 *qhi, *qlo, *khi, *klo, *ihi, *ilo, *whi, *wlo;
    bf16 *ctxhi, *ctxlo, *vhiT, *vloT;
    unsigned int* m32;
    cudaGetSymbolAddress((void**)&vh,    g_vh);
    cudaGetSymbolAddress((void**)&fc,    g_fc);
    cudaGetSymbolAddress((void**)&qhi,   g_qhi);
    cudaGetSymbolAddress((void**)&qlo,   g_qlo);
    cudaGetSymbolAddress((void**)&khi,   g_khi);
    cudaGetSymbolAddress((void**)&klo,   g_klo);
    cudaGetSymbolAddress((void**)&ihi,   g_ihi);
    cudaGetSymbolAddress((void**)&ilo,   g_ilo);
    cudaGetSymbolAddress((void**)&whi,   g_whi);
    cudaGetSymbolAddress((void**)&wlo,   g_wlo);
    cudaGetSymbolAddress((void**)&ctxhi, g_ctxhi);
    cudaGetSymbolAddress((void**)&ctxlo, g_ctxlo);
    cudaGetSymbolAddress((void**)&vhiT,  g_vhiT);
    cudaGetSymbolAddress((void**)&vloT,  g_vloT);
    cudaGetSymbolAddress((void**)&m32,   g_mask32);

    cudaFuncSetAttribute(attn_fused_kernel,
                         cudaFuncAttributeMaxDynamicSharedMemorySize, AF_SMEM_BYTES);
    cudaFuncSetAttribute(qkv_hmma_kernel,
                         cudaFuncAttributeMaxDynamicSharedMemorySize, HMMA_SMEM);
    cudaFuncSetAttribute(fc_hmma_kernel,
                         cudaFuncAttributeMaxDynamicSharedMemorySize, HMMA_SMEM);

    // mask -> bit-packed
    mask_pack_kernel<<<(B_ * L_ * L_ / 32) / 256, 256>>>(mask, m32);

    // input + weight splits
    dim3 gsi((B_ * L_ * E_) / (4 * 256), 3);
    split_in_kernel<<<gsi, 256>>>(q, k, v, ihi, ilo);
    dim3 gsw((E_ * E_) / (4 * 256), 4);
    split_w_kernel<<<gsw, 256>>>(Wq, Wk, Wv, Wfc, whi, wlo);

    // QKV projections via HMMA
    dim3 gqkv(E_ / 128, (B_ * L_) / 128, 3);
    qkv_hmma_kernel<<<gqkv, 256, HMMA_SMEM>>>(ihi, ilo, whi, wlo, bq, bk, bv,
                                              qhi, qlo, khi, klo, vh);

    // V transpose + split
    dim3 gvt(H_ * B_, L_ / 64);
    vT_kernel<<<gvt, 256>>>(vh, vhiT, vloT);

    // fused attention (two-pass recompute, register-reuse AV, LDSM)
    dim3 gaf(L_ / 128, H_ * B_);              // (16, 32)
    attn_fused_kernel<<<gaf, 256, AF_SMEM_BYTES>>>(
        qhi, qlo, khi, klo, vhiT, vloT, m32, attn, ctxhi, ctxlo);

    // FC via HMMA
    dim3 gfc(E_ / 128, (B_ * L_) / 128);
    fc_hmma_kernel<<<gfc, 256, HMMA_SMEM>>>(ctxhi, ctxlo, whi, wlo, bfc, fc);

    // residual + LayerNorm
    ln_kernel<<<B_ * L_, 256>>>(fc, q, gamma, beta, out);
}

// round 14
// speedup vs baseline: 1.0618x; 1.0618x over previous
#include <cuda_runtime.h>
#include <cuda_bf16.h>
#include <cstdint>
#include <cstddef>

#define B_ 4
#define L_ 2048
#define E_ 512
#define H_ 8
#define DK_ 64
#define DV_ 64
#define GP 72          // smem pitch (bf16), 144B == 16 mod 128 -> LDSM conflict-free

typedef __nv_bfloat16 bf16;
typedef __nv_bfloat162 bf162;

// ---- scratch (device globals; no allocations allowed) ----
__device__ float g_fc[B_ * L_ * E_];
__device__ float g_inv[H_ * B_ * L_];          // 1/rowsum per (z,row)
__device__ bf16 g_qhi[B_ * L_ * E_];
__device__ bf16 g_qlo[B_ * L_ * E_];
__device__ bf16 g_khi[B_ * L_ * E_];
__device__ bf16 g_klo[B_ * L_ * E_];
__device__ bf16 g_vhi[B_ * L_ * E_];
__device__ bf16 g_vlo[B_ * L_ * E_];
__device__ bf16 g_ihi[3 * B_ * L_ * E_];
__device__ bf16 g_ilo[3 * B_ * L_ * E_];
__device__ bf16 g_whi[4 * E_ * E_];
__device__ bf16 g_wlo[4 * E_ * E_];
__device__ bf16 g_ctxhi[B_ * L_ * E_];
__device__ bf16 g_ctxlo[B_ * L_ * E_];
__device__ unsigned int g_mask32[B_ * L_ * L_ / 32];  // bit-packed mask

// ============================================================================
__device__ __forceinline__ void mma16816(float* c, uint32_t a0, uint32_t a1,
                                         uint32_t a2, uint32_t a3,
                                         uint32_t b0, uint32_t b1) {
    asm volatile(
        "mma.sync.aligned.m16n8k16.row.col.f32.bf16.bf16.f32 "
        "{%0,%1,%2,%3}, {%4,%5,%6,%7}, {%8,%9}, {%0,%1,%2,%3};"
        : "+f"(c[0]), "+f"(c[1]), "+f"(c[2]), "+f"(c[3])
        : "r"(a0), "r"(a1), "r"(a2), "r"(a3), "r"(b0), "r"(b1));
}

#define LDSM_X4(r0, r1, r2, r3, addr) \
    asm volatile("ldmatrix.sync.aligned.m8n8.x4.shared.b16 {%0,%1,%2,%3}, [%4];" \
        : "=r"(r0), "=r"(r1), "=r"(r2), "=r"(r3) : "r"(addr))

#define LDSM_X4_T(r0, r1, r2, r3, addr) \
    asm volatile("ldmatrix.sync.aligned.m8n8.x4.trans.shared.b16 {%0,%1,%2,%3}, [%4];" \
        : "=r"(r0), "=r"(r1), "=r"(r2), "=r"(r3) : "r"(addr))

__device__ __forceinline__ uint32_t smem_u32(const void* p) {
    uint32_t a;
    asm("{ .reg .u64 t; cvta.to.shared.u64 t, %1; cvt.u32.u64 %0, t; }"
        : "=r"(a) : "l"(p));
    return a;
}

__device__ __forceinline__ void split2(float f, bf16& hi, bf16& lo) {
    hi = __float2bfloat16_rn(f);
    lo = __float2bfloat16_rn(f - __bfloat162float(hi));
}

__device__ __forceinline__ uint32_t packbf2(bf16 x, bf16 y) {
    bf162 t; t.x = x; t.y = y;
    return *(uint32_t*)&t;
}

// LDSM per-thread byte offsets (non-trans validated R12; trans derived).
__device__ __forceinline__ uint32_t a_ldsm_off(int lane, int ar0, int pitch) {
    return (uint32_t)(((ar0 + (lane & 15)) * pitch + ((lane >> 1) & 8)) * 2);
}
__device__ __forceinline__ uint32_t b_ldsm_off(int lane, int pitch) {
    return (uint32_t)((((lane & 7) + ((lane >> 1) & 8)) * pitch + (lane & 8)) * 2);
}
// trans-B from [k][n]: lanes 0-15 rows k0..k0+15 col 0; lanes 16-31 same rows col +8
__device__ __forceinline__ uint32_t bt_ldsm_off(int lane, int pitch) {
    return (uint32_t)(((lane & 15) * pitch + ((lane >> 4) * 8)) * 2);
}

// ============================================================================
// Fused attention, SINGLE pass: scores (HMMA hi/lo, LDSM) -> mask -> exp ->
//   write unnormalized exp to attn (once) + rowsum + AV accumulate (P in regs,
//   V via trans-LDSM). Epilogue: ctx *= 1/rowsum, g_inv out.
// CTA = 128 q-rows of one z = h*B + b. 256 threads, 2 CTAs/SM.
// ============================================================================
__global__ __launch_bounds__(256, 2) void attn_fused_kernel(
    const bf16* __restrict__ qhi, const bf16* __restrict__ qlo,
    const bf16* __restrict__ khi, const bf16* __restrict__ klo,
    const bf16* __restrict__ vhi, const bf16* __restrict__ vlo,
    const unsigned int* __restrict__ m32,
    float* __restrict__ attn, float* __restrict__ ginv,
    bf16* __restrict__ ctxhi, bf16* __restrict__ ctxlo)
{
    extern __shared__ __align__(16) char smem[];
    bf16* sQh = (bf16*)smem;                  // 128 x GP each
    bf16* sQl = sQh + 128 * GP;
    bf16* sKh = sQl + 128 * GP;
    bf16* sKl = sKh + 128 * GP;
    bf16* sVh = sKl + 128 * GP;               // [token(128)][n(64)] pitch GP
    bf16* sVl = sVh + 128 * GP;
    float* sinv = (float*)(sVl + 128 * GP);   // 128

    int tid = threadIdx.x, lane = tid & 31, w = tid >> 5;
    int row0 = blockIdx.x * 128;
    int z = blockIdx.y, h = z / B_, b = z % B_;

    // ---- Q tile (persistent) ----
    {
        int r = tid >> 1, half = tid & 1;
        size_t qo = ((size_t)(b * L_ + row0 + r) * E_) + h * DK_ + half * 32;
        const uint4* gqh = (const uint4*)(qhi + qo);
        const uint4* gql = (const uint4*)(qlo + qo);
        uint4* dqh = (uint4*)(sQh + r * GP + half * 32);
        uint4* dql = (uint4*)(sQl + r * GP + half * 32);
#pragma unroll
        for (int i = 0; i < 4; i++) { dqh[i] = gqh[i]; dql[i] = gql[i]; }
    }

    int lr0 = w * 16 + (lane >> 2);
    int r0g = row0 + lr0;

    uint32_t uQh = smem_u32(sQh), uQl = smem_u32(sQl);
    uint32_t uKh = smem_u32(sKh), uKl = smem_u32(sKl);
    uint32_t uVh = smem_u32(sVh), uVl = smem_u32(sVl);
    uint32_t aoff = a_ldsm_off(lane, w * 16, GP);
    uint32_t boffK = b_ldsm_off(lane, GP);
    uint32_t boffVt = bt_ldsm_off(lane, GP);

    const size_t mb = (size_t)b * L_ * L_;
    const unsigned int* M0 = m32 + ((mb + (size_t)r0g * L_) >> 5);
    const unsigned int* M1 = m32 + ((mb + (size_t)(r0g + 8) * L_) >> 5);
    float* Az = attn + (size_t)z * L_ * L_;

    float rs0 = 0.f, rs1 = 0.f;
    float accv[8][4];
#pragma unroll
    for (int nb = 0; nb < 8; nb++)
#pragma unroll
        for (int j = 0; j < 4; j++) accv[nb][j] = 0.f;

    for (int kt = 0; kt < 16; kt++) {
        int k0 = kt * 128;
        __syncthreads();
        {   // K tile: 128 keys x 64 dk ; V tile: 128 tokens x 64 dv
            int r = tid >> 1, half = tid & 1;
            size_t ko = ((size_t)(b * L_ + k0 + r) * E_) + h * DK_ + half * 32;
            const uint4* gkh = (const uint4*)(khi + ko);
            const uint4* gkl = (const uint4*)(klo + ko);
            const uint4* gvh = (const uint4*)(vhi + ko);
            const uint4* gvl = (const uint4*)(vlo + ko);
            uint4* dkh = (uint4*)(sKh + r * GP + half * 32);
            uint4* dkl = (uint4*)(sKl + r * GP + half * 32);
            uint4* dvh = (uint4*)(sVh + r * GP + half * 32);
            uint4* dvl = (uint4*)(sVl + r * GP + half * 32);
#pragma unroll
            for (int i = 0; i < 4; i++) {
                dkh[i] = gkh[i]; dkl[i] = gkl[i];
                dvh[i] = gvh[i]; dvl[i] = gvl[i];
            }
        }
        __syncthreads();

        // ---- scores: 128x128, 3-pass hi/lo ----
        float acc[16][4];
#pragma unroll
        for (int nb = 0; nb < 16; nb++)
#pragma unroll
            for (int j = 0; j < 4; j++) acc[nb][j] = 0.f;
#pragma unroll
        for (int pass = 0; pass < 3; pass++) {
            uint32_t aB = ((pass == 2) ? uQl : uQh) + aoff;
            uint32_t bB = ((pass == 1) ? uKl : uKh) + boffK;
#pragma unroll
            for (int ks = 0; ks < 4; ks++) {
                uint32_t a0, a1, a2, a3;
                LDSM_X4(a0, a1, a2, a3, aB + ks * 32);
#pragma unroll
                for (int j = 0; j < 8; j++) {
                    uint32_t b0, b1, b2, b3;
                    LDSM_X4(b0, b1, b2, b3, bB + j * (16 * GP * 2) + ks * 32);
                    mma16816(acc[2 * j],     a0, a1, a2, a3, b0, b1);
                    mma16816(acc[2 * j + 1], a0, a1, a2, a3, b2, b3);
                }
            }
        }

        // ---- mask + exp -> attn (unnormalized) + rowsums, keep P in acc ----
        int wb = k0 >> 5;
        unsigned int mw0[4] = {M0[wb], M0[wb + 1], M0[wb + 2], M0[wb + 3]};
        unsigned int mw1[4] = {M1[wb], M1[wb + 1], M1[wb + 2], M1[wb + 3]};
#pragma unroll
        for (int nb = 0; nb < 16; nb++) {
            int cl = nb * 8 + (lane & 3) * 2;
            int cg = k0 + cl;
            unsigned int b0m = (mw0[cl >> 5] >> (cl & 31)) & 3u;
            unsigned int b1m = (mw1[cl >> 5] >> (cl & 31)) & 3u;
            float p00 = (b0m & 1u) ? 0.f : __expf(acc[nb][0] * 0.125f);
            float p01 = (b0m & 2u) ? 0.f : __expf(acc[nb][1] * 0.125f);
            float p10 = (b1m & 1u) ? 0.f : __expf(acc[nb][2] * 0.125f);
            float p11 = (b1m & 2u) ? 0.f : __expf(acc[nb][3] * 0.125f);
            __stcs((float2*)(Az + (size_t)r0g * L_ + cg), make_float2(p00, p01));
            __stcs((float2*)(Az + (size_t)(r0g + 8) * L_ + cg), make_float2(p10, p11));
            rs0 += p00 + p01;
            rs1 += p10 + p11;
            acc[nb][0] = p00; acc[nb][1] = p01;
            acc[nb][2] = p10; acc[nb][3] = p11;
        }

        // ---- AV: accv += P @ V, P in registers, V via trans-LDSM ----
#pragma unroll
        for (int ks = 0; ks < 8; ks++) {
            int n0 = 2 * ks, n1 = n0 + 1;
            bf16 h00, l00, h01, l01, h10, l10, h11, l11;
            split2(acc[n0][0], h00, l00); split2(acc[n0][1], h01, l01);
            split2(acc[n0][2], h10, l10); split2(acc[n0][3], h11, l11);
            uint32_t ah0 = packbf2(h00, h01), al0 = packbf2(l00, l01);
            uint32_t ah1 = packbf2(h10, h11), al1 = packbf2(l10, l11);
            split2(acc[n1][0], h00, l00); split2(acc[n1][1], h01, l01);
            split2(acc[n1][2], h10, l10); split2(acc[n1][3], h11, l11);
            uint32_t ah2 = packbf2(h00, h01), al2 = packbf2(l00, l01);
            uint32_t ah3 = packbf2(h10, h11), al3 = packbf2(l10, l11);
            uint32_t kofs = (uint32_t)(ks * 16 * GP * 2);
#pragma unroll
            for (int j = 0; j < 4; j++) {
                uint32_t bh0, bh1, bh2, bh3, bl0, bl1, bl2, bl3;
                LDSM_X4_T(bh0, bh1, bh2, bh3, uVh + boffVt + kofs + j * 32);
                LDSM_X4_T(bl0, bl1, bl2, bl3, uVl + boffVt + kofs + j * 32);
                mma16816(accv[2 * j], ah0, ah1, ah2, ah3, bh0, bh1);
                mma16816(accv[2 * j], ah0, ah1, ah2, ah3, bl0, bl1);
                mma16816(accv[2 * j], al0, al1, al2, al3, bh0, bh1);
                mma16816(accv[2 * j + 1], ah0, ah1, ah2, ah3, bh2, bh3);
                mma16816(accv[2 * j + 1], ah0, ah1, ah2, ah3, bl2, bl3);
                mma16816(accv[2 * j + 1], al0, al1, al2, al3, bh2, bh3);
            }
        }
    }

    // ---- rowsums -> sinv / g_inv ----
    rs0 += __shfl_xor_sync(0xffffffffu, rs0, 1);
    rs0 += __shfl_xor_sync(0xffffffffu, rs0, 2);
    rs1 += __shfl_xor_sync(0xffffffffu, rs1, 1);
    rs1 += __shfl_xor_sync(0xffffffffu, rs1, 2);
    if ((lane & 3) == 0) {
        sinv[lr0] = 1.0f / rs0;
        sinv[lr0 + 8] = 1.0f / rs1;
    }
    __syncthreads();
    if (tid < 128) ginv[(size_t)z * L_ + row0 + tid] = sinv[tid];
    float inv0 = sinv[lr0], inv1 = sinv[lr0 + 8];

    // ---- ctx epilogue: scale by inv, emit hi/lo ----
#pragma unroll
    for (int nb = 0; nb < 8; nb++) {
        int cg = nb * 8 + (lane & 3) * 2;
        size_t o0 = ((size_t)(b * L_ + r0g)) * E_ + h * DV_ + cg;
        size_t o1 = ((size_t)(b * L_ + r0g + 8)) * E_ + h * DV_ + cg;
        bf162 h2, l2;
        split2(accv[nb][0] * inv0, h2.x, l2.x);
        split2(accv[nb][1] * inv0, h2.y, l2.y);
        *(bf162*)(ctxhi + o0) = h2;
        *(bf162*)(ctxlo + o0) = l2;
        split2(accv[nb][2] * inv1, h2.x, l2.x);
        split2(accv[nb][3] * inv1, h2.y, l2.y);
        *(bf162*)(ctxhi + o1) = h2;
        *(bf162*)(ctxlo + o1) = l2;
    }
}
#define AF_SMEM_BYTES (6 * 128 * GP * 2 + 512)

// ============================================================================
// HMMA NT GEMM body (LDSM, validated): C = A @ B^T + bias; explicit tile coords
// ============================================================================
__device__ __forceinline__ void hmma_nt_body(
    const bf16* __restrict__ Ahi, const bf16* __restrict__ Alo,
    const bf16* __restrict__ Bhi, const bf16* __restrict__ Blo,
    const float* __restrict__ bias,
    float* __restrict__ Cf, bf16* __restrict__ Chi, bf16* __restrict__ Clo,
    int K, int ldc, int row0, int col0)
{
    extern __shared__ __align__(16) char smem[];
    bf16* sAh = (bf16*)smem;
    bf16* sAl = sAh + 128 * GP;
    bf16* sBh = sAl + 128 * GP;
    bf16* sBl = sBh + 128 * GP;

    int tid = threadIdx.x, lane = tid & 31, w = tid >> 5;

    float acc[16][4];
#pragma unroll
    for (int nb = 0; nb < 16; nb++)
#pragma unroll
        for (int j = 0; j < 4; j++) acc[nb][j] = 0.f;

    int r = tid >> 1, half = tid & 1;
    const bf16* gAh = Ahi + (size_t)(row0 + r) * K + half * 32;
    const bf16* gAl = Alo + (size_t)(row0 + r) * K + half * 32;
    const bf16* gBh = Bhi + (size_t)(col0 + r) * K + half * 32;
    const bf16* gBl = Blo + (size_t)(col0 + r) * K + half * 32;
    bf16* dAh = sAh + r * GP + half * 32;
    bf16* dAl = sAl + r * GP + half * 32;
    bf16* dBh = sBh + r * GP + half * 32;
    bf16* dBl = sBl + r * GP + half * 32;

    uint32_t uAh = smem_u32(sAh), uAl = smem_u32(sAl);
    uint32_t uBh = smem_u32(sBh), uBl = smem_u32(sBl);
    uint32_t aoff = a_ldsm_off(lane, w * 16, GP);
    uint32_t boff = b_ldsm_off(lane, GP);

    for (int k0 = 0; k0 < K; k0 += 64) {
        __syncthreads();
        const uint4* a4h = (const uint4*)(gAh + k0);
        const uint4* a4l = (const uint4*)(gAl + k0);
        const uint4* b4h = (const uint4*)(gBh + k0);
        const uint4* b4l = (const uint4*)(gBl + k0);
#pragma unroll
        for (int i = 0; i < 4; i++) {
            ((uint4*)dAh)[i] = a4h[i];
            ((uint4*)dAl)[i] = a4l[i];
            ((uint4*)dBh)[i] = b4h[i];
            ((uint4*)dBl)[i] = b4l[i];
        }
        __syncthreads();
#pragma unroll
        for (int pass = 0; pass < 3; pass++) {
            uint32_t aB = ((pass == 2) ? uAl : uAh) + aoff;
            uint32_t bB = ((pass == 1) ? uBl : uBh) + boff;
#pragma unroll
            for (int ks = 0; ks < 4; ks++) {
                uint32_t a0, a1, a2, a3;
                LDSM_X4(a0, a1, a2, a3, aB + ks * 32);
#pragma unroll
                for (int j = 0; j < 8; j++) {
                    uint32_t b0, b1, b2, b3;
                    LDSM_X4(b0, b1, b2, b3, bB + j * (16 * GP * 2) + ks * 32);
                    mma16816(acc[2 * j],     a0, a1, a2, a3, b0, b1);
                    mma16816(acc[2 * j + 1], a0, a1, a2, a3, b2, b3);
                }
            }
        }
    }

    int r0g = row0 + w * 16 + (lane >> 2);
#pragma unroll
    for (int nb = 0; nb < 16; nb++) {
        int cg = col0 + nb * 8 + (lane & 3) * 2;
        float f00 = acc[nb][0] + bias[cg];
        float f01 = acc[nb][1] + bias[cg + 1];
        float f10 = acc[nb][2] + bias[cg];
        float f11 = acc[nb][3] + bias[cg + 1];
        if (Cf) {
            *(float2*)(Cf + (size_t)r0g * ldc + cg) = make_float2(f00, f01);
            *(float2*)(Cf + (size_t)(r0g + 8) * ldc + cg) = make_float2(f10, f11);
        }
        if (Chi) {
            bf162 h2, l2;
            split2(f00, h2.x, l2.x); split2(f01, h2.y, l2.y);
            *(bf162*)(Chi + (size_t)r0g * ldc + cg) = h2;
            *(bf162*)(Clo + (size_t)r0g * ldc + cg) = l2;
            split2(f10, h2.x, l2.x); split2(f11, h2.y, l2.y);
            *(bf162*)(Chi + (size_t)(r0g + 8) * ldc + cg) = h2;
            *(bf162*)(Clo + (size_t)(r0g + 8) * ldc + cg) = l2;
        }
    }
}
#define HMMA_SMEM (4 * 128 * GP * 2)

// ============================================================================
// qkv (z=0..2, tensor-bound) + mask bit-pack (z=3, memory-bound) in ONE launch
// ============================================================================
__global__ __launch_bounds__(256, 2) void qkv_mask_kernel(
    const bf16* __restrict__ ihi, const bf16* __restrict__ ilo,
    const bf16* __restrict__ whi, const bf16* __restrict__ wlo,
    const float* __restrict__ bq, const float* __restrict__ bk,
    const float* __restrict__ bv,
    bf16* __restrict__ qhi, bf16* __restrict__ qlo,
    bf16* __restrict__ khi, bf16* __restrict__ klo,
    bf16* __restrict__ vhi, bf16* __restrict__ vlo,
    const void* __restrict__ mask, unsigned int* __restrict__ m32)
{
    int zz = blockIdx.z;
    if (zz < 3) {
        const bf16* Ahi = ihi + (size_t)zz * (B_ * L_ * E_);
        const bf16* Alo = ilo + (size_t)zz * (B_ * L_ * E_);
        const bf16* Bhi = whi + (size_t)zz * (E_ * E_);
        const bf16* Blo = wlo + (size_t)zz * (E_ * E_);
        const float* bias = (zz == 0) ? bq : (zz == 1) ? bk : bv;
        bf16* Chi = (zz == 0) ? qhi : (zz == 1) ? khi : vhi;
        bf16* Clo = (zz == 0) ? qlo : (zz == 1) ? klo : vlo;
        hmma_nt_body(Ahi, Alo, Bhi, Blo, bias, nullptr, Chi, Clo, E_, E_,
                     blockIdx.y * 128, blockIdx.x * 128);
        return;
    }
    // ---- mask pack: 256 blocks x 2048 words = 524288 words total ----
    __shared__ int s_byte;
    int tid = threadIdx.x;
    if (tid == 0) {
        const unsigned int* mi = (const unsigned int*)mask;
        int bm = 0;
#pragma unroll 8
        for (int i = 0; i < 64; i++) if (mi[i] > 1u) bm = 1;
        s_byte = bm;
    }
    __syncthreads();
    int blk = blockIdx.y * 4 + blockIdx.x;   // 0..255
    int sb = s_byte;
#pragma unroll 2
    for (int it = 0; it < 8; it++) {
        size_t widx = (size_t)blk * 2048 + it * 256 + tid;
        unsigned int wv = 0;
        if (sb) {
            const unsigned int* p = (const unsigned int*)mask + widx * 8;
#pragma unroll
            for (int j = 0; j < 8; j++) {
                unsigned int v = p[j];
                if (v & 0x000000FFu) wv |= 1u << (j * 4 + 0);
                if (v & 0x0000FF00u) wv |= 1u << (j * 4 + 1);
                if (v & 0x00FF0000u) wv |= 1u << (j * 4 + 2);
                if (v & 0xFF000000u) wv |= 1u << (j * 4 + 3);
            }
        } else {
            const int4* p = (const int4*)mask + widx * 8;
#pragma unroll
            for (int j = 0; j < 8; j++) {
                int4 v = p[j];
                if (v.x) wv |= 1u << (j * 4 + 0);
                if (v.y) wv |= 1u << (j * 4 + 1);
                if (v.z) wv |= 1u << (j * 4 + 2);
                if (v.w) wv |= 1u << (j * 4 + 3);
            }
        }
        m32[widx] = wv;
    }
}

// ============================================================================
// prep: input splits (y=0..2) + weight splits (y=3)
// ============================================================================
__global__ void prep_kernel(const float* __restrict__ q,
                            const float* __restrict__ k,
                            const float* __restrict__ v,
                            const float* __restrict__ Wq,
                            const float* __restrict__ Wk,
                            const float* __restrict__ Wv,
                            const float* __restrict__ Wfc,
                            bf16* __restrict__ ihi, bf16* __restrict__ ilo,
                            bf16* __restrict__ whi, bf16* __restrict__ wlo)
{
    int y = blockIdx.y;
    if (y < 3) {
        const float* src = (y == 0) ? q : (y == 1) ? k : v;
        bf16* hi = ihi + (size_t)y * (B_ * L_ * E_);
        bf16* lo = ilo + (size_t)y * (B_ * L_ * E_);
        size_t i = ((size_t)blockIdx.x * 256 + threadIdx.x) * 4;
        float4 a = *(const float4*)(src + i);
#pragma unroll
        for (int j = 0; j < 4; j++) {
            bf16 h, l;
            split2(((const float*)&a)[j], h, l);
            hi[i + j] = h; lo[i + j] = l;
        }
    } else {
        if (blockIdx.x >= 1024) return;
        int which = blockIdx.x >> 8;
        int xx = blockIdx.x & 255;
        const float* src = (which == 0) ? Wq : (which == 1) ? Wk
                         : (which == 2) ? Wv : Wfc;
        bf16* hi = whi + (size_t)which * (E_ * E_);
        bf16* lo = wlo + (size_t)which * (E_ * E_);
        size_t i = ((size_t)xx * 256 + threadIdx.x) * 4;
        float4 a = *(const float4*)(src + i);
#pragma unroll
        for (int j = 0; j < 4; j++) {
            bf16 h, l;
            split2(((const float*)&a)[j], h, l);
            hi[i + j] = h; lo[i + j] = l;
        }
    }
}

// ============================================================================
// finish1: fc GEMM (x < 256) + attn normalization sweep half 1
// finish2: LayerNorm (x < 8192) + sweep half 2
// ============================================================================
#define SWEEP_BLOCKS 1024
#define SWEEP_F4     16384     // float4 per sweep block (half slab / 1024)

__device__ __forceinline__ void sweep_chunk(float* __restrict__ attn,
                                            const float* __restrict__ ginv,
                                            size_t base_f4)
{
    float4* A4 = (float4*)attn;
    int tid = threadIdx.x;
#pragma unroll 4
    for (int it = 0; it < SWEEP_F4 / 256; it++) {
        size_t f = base_f4 + (size_t)it * 256 + tid;
        float inv = __ldg(ginv + (f >> 9));      // 512 float4 per row
        float4 vv = __ldcs(A4 + f);
        vv.x *= inv; vv.y *= inv; vv.z *= inv; vv.w *= inv;
        __stcs(A4 + f, vv);
    }
}

__global__ __launch_bounds__(256, 2) void finish1_kernel(
    const bf16* __restrict__ ctxhi, const bf16* __restrict__ ctxlo,
    const bf16* __restrict__ whi, const bf16* __restrict__ wlo,
    const float* __restrict__ bfc, float* __restrict__ fc,
    float* __restrict__ attn, const float* __restrict__ ginv)
{
    if (blockIdx.x < 256) {
        hmma_nt_body(ctxhi, ctxlo, whi + 3 * (E_ * E_), wlo + 3 * (E_ * E_),
                     bfc, fc, nullptr, nullptr, E_, E_,
                     (blockIdx.x >> 2) * 128, (blockIdx.x & 3) * 128);
    } else {
        sweep_chunk(attn, ginv, (size_t)(blockIdx.x - 256) * SWEEP_F4);
    }
}

__global__ void finish2_kernel(
    const float* __restrict__ fc, const float* __restrict__ resid,
    const float* __restrict__ gamma, const float* __restrict__ beta,
    float* __restrict__ out,
    float* __restrict__ attn, const float* __restrict__ ginv)
{
    if (blockIdx.x >= 8192) {
        sweep_chunk(attn, ginv,
                    (size_t)SWEEP_BLOCKS * SWEEP_F4 +
                    (size_t)(blockIdx.x - 8192) * SWEEP_F4);
        return;
    }
    size_t base = (size_t)blockIdx.x * E_;
    int tid = threadIdx.x;
    float x0 = fc[base + tid] + resid[base + tid];
    float x1 = fc[base + tid + 256] + resid[base + tid + 256];
    float s = x0 + x1;
    float ss = x0 * x0 + x1 * x1;

    __shared__ float rs[8], rss[8];
#pragma unroll
    for (int o = 16; o; o >>= 1) {
        s  += __shfl_xor_sync(0xffffffffu, s, o);
        ss += __shfl_xor_sync(0xffffffffu, ss, o);
    }
    if ((tid & 31) == 0) { rs[tid >> 5] = s; rss[tid >> 5] = ss; }
    __syncthreads();
    s = 0.f; ss = 0.f;
#pragma unroll
    for (int i = 0; i < 8; i++) { s += rs[i]; ss += rss[i]; }

    float mu = s * (1.0f / E_);
    float var = ss * (1.0f / E_) - mu * mu;
    float rstd = rsqrtf(var + 1e-5f);
    out[base + tid]       = (x0 - mu) * rstd * gamma[tid] + beta[tid];
    out[base + tid + 256] = (x1 - mu) * rstd * gamma[tid + 256] + beta[tid + 256];
}

// ============================================================================
extern "C" void kernel_launch(void* const* d_in, const int* in_sizes, int n_in,
                              void* d_out, int out_size)
{
    const float* q    = (const float*)d_in[0];
    const float* k    = (const float*)d_in[1];
    const float* v    = (const float*)d_in[2];
    const void*  mask = (const void*)d_in[3];
    const float* Wq   = (const float*)d_in[4];
    const float* bq   = (const float*)d_in[5];
    const float* Wk   = (const float*)d_in[6];
    const float* bk   = (const float*)d_in[7];
    const float* Wv   = (const float*)d_in[8];
    const float* bv   = (const float*)d_in[9];
    const float* Wfc  = (const float*)d_in[10];
    const float* bfc  = (const float*)d_in[11];
    const float* gamma = (const float*)d_in[12];
    const float* beta  = (const float*)d_in[13];

    float* out  = (float*)d_out;
    float* attn = out + (size_t)B_ * L_ * E_;

    float *fc, *ginv;
    bf16 *qhi, *qlo, *khi, *klo, *vhi, *vlo, *ihi, *ilo, *whi, *wlo;
    bf16 *ctxhi, *ctxlo;
    unsigned int* m32;
    cudaGetSymbolAddress((void**)&fc,    g_fc);
    cudaGetSymbolAddress((void**)&ginv,  g_inv);
    cudaGetSymbolAddress((void**)&qhi,   g_qhi);
    cudaGetSymbolAddress((void**)&qlo,   g_qlo);
    cudaGetSymbolAddress((void**)&khi,   g_khi);
    cudaGetSymbolAddress((void**)&klo,   g_klo);
    cudaGetSymbolAddress((void**)&vhi,   g_vhi);
    cudaGetSymbolAddress((void**)&vlo,   g_vlo);
    cudaGetSymbolAddress((void**)&ihi,   g_ihi);
    cudaGetSymbolAddress((void**)&ilo,   g_ilo);
    cudaGetSymbolAddress((void**)&whi,   g_whi);
    cudaGetSymbolAddress((void**)&wlo,   g_wlo);
    cudaGetSymbolAddress((void**)&ctxhi, g_ctxhi);
    cudaGetSymbolAddress((void**)&ctxlo, g_ctxlo);
    cudaGetSymbolAddress((void**)&m32,   g_mask32);

    cudaFuncSetAttribute(attn_fused_kernel,
                         cudaFuncAttributeMaxDynamicSharedMemorySize, AF_SMEM_BYTES);
    cudaFuncSetAttribute(qkv_mask_kernel,
                         cudaFuncAttributeMaxDynamicSharedMemorySize, HMMA_SMEM);
    cudaFuncSetAttribute(finish1_kernel,
                         cudaFuncAttributeMaxDynamicSharedMemorySize, HMMA_SMEM);

    // prep: input + weight hi/lo splits
    dim3 gprep((B_ * L_ * E_) / (4 * 256), 4);       // (4096, 4)
    prep_kernel<<<gprep, 256>>>(q, k, v, Wq, Wk, Wv, Wfc, ihi, ilo, whi, wlo);

    // qkv (tensor) + mask pack (memory) overlapped
    dim3 gqm(E_ / 128, (B_ * L_) / 128, 4);          // (4, 64, 4)
    qkv_mask_kernel<<<gqm, 256, HMMA_SMEM>>>(ihi, ilo, whi, wlo, bq, bk, bv,
                                             qhi, qlo, khi, klo, vhi, vlo,
                                             mask, m32);

    // fused single-pass attention
    dim3 gaf(L_ / 128, H_ * B_);                     // (16, 32)
    attn_fused_kernel<<<gaf, 256, AF_SMEM_BYTES>>>(
        qhi, qlo, khi, klo, vhi, vlo, m32, attn, ginv, ctxhi, ctxlo);

    // fc (tensor) + sweep half1 (memory) overlapped
    finish1_kernel<<<256 + SWEEP_BLOCKS, 256, HMMA_SMEM>>>(
        ctxhi, ctxlo, whi, wlo, bfc, fc, attn, ginv);

    // ln (memory) + sweep half2 (memory)
    finish2_kernel<<<8192 + SWEEP_BLOCKS, 256>>>(
        fc, q, gamma, beta, out, attn, ginv);
}

// round 15
// speedup vs baseline: 1.0684x; 1.0062x over previous
#include <cuda_runtime.h>
#include <cuda_bf16.h>
#include <cstdint>
#include <cstddef>

#define B_ 4
#define L_ 2048
#define E_ 512
#define H_ 8
#define DK_ 64
#define DV_ 64
#define GP 72          // smem pitch (bf16), 144B == 16 mod 128 -> LDSM conflict-free

typedef __nv_bfloat16 bf16;
typedef __nv_bfloat162 bf162;

// ---- scratch (device globals; no allocations allowed) ----
__device__ float g_fc[B_ * L_ * E_];
__device__ float g_inv[H_ * B_ * L_];          // 1/rowsum per (z,row)
__device__ bf16 g_qhi[B_ * L_ * E_];
__device__ bf16 g_qlo[B_ * L_ * E_];
__device__ bf16 g_khi[B_ * L_ * E_];
__device__ bf16 g_klo[B_ * L_ * E_];
__device__ bf16 g_vhi[B_ * L_ * E_];
__device__ bf16 g_vlo[B_ * L_ * E_];
__device__ bf16 g_ctxhi[B_ * L_ * E_];
__device__ bf16 g_ctxlo[B_ * L_ * E_];
__device__ unsigned int g_mask32[B_ * L_ * L_ / 32];  // bit-packed mask

// ============================================================================
__device__ __forceinline__ void mma16816(float* c, uint32_t a0, uint32_t a1,
                                         uint32_t a2, uint32_t a3,
                                         uint32_t b0, uint32_t b1) {
    asm volatile(
        "mma.sync.aligned.m16n8k16.row.col.f32.bf16.bf16.f32 "
        "{%0,%1,%2,%3}, {%4,%5,%6,%7}, {%8,%9}, {%0,%1,%2,%3};"
        : "+f"(c[0]), "+f"(c[1]), "+f"(c[2]), "+f"(c[3])
        : "r"(a0), "r"(a1), "r"(a2), "r"(a3), "r"(b0), "r"(b1));
}

#define LDSM_X4(r0, r1, r2, r3, addr) \
    asm volatile("ldmatrix.sync.aligned.m8n8.x4.shared.b16 {%0,%1,%2,%3}, [%4];" \
        : "=r"(r0), "=r"(r1), "=r"(r2), "=r"(r3) : "r"(addr))

#define LDSM_X4_T(r0, r1, r2, r3, addr) \
    asm volatile("ldmatrix.sync.aligned.m8n8.x4.trans.shared.b16 {%0,%1,%2,%3}, [%4];" \
        : "=r"(r0), "=r"(r1), "=r"(r2), "=r"(r3) : "r"(addr))

__device__ __forceinline__ uint32_t smem_u32(const void* p) {
    uint32_t a;
    asm("{ .reg .u64 t; cvta.to.shared.u64 t, %1; cvt.u32.u64 %0, t; }"
        : "=r"(a) : "l"(p));
    return a;
}

__device__ __forceinline__ void split2(float f, bf16& hi, bf16& lo) {
    hi = __float2bfloat16_rn(f);
    lo = __float2bfloat16_rn(f - __bfloat162float(hi));
}

__device__ __forceinline__ uint32_t packbf2(bf16 x, bf16 y) {
    bf162 t; t.x = x; t.y = y;
    return *(uint32_t*)&t;
}

// exp(s/8) via single ex2: s * 0.125 * log2(e)
__device__ __forceinline__ float fexp8(float s) {
    float r;
    asm("ex2.approx.f32 %0, %1;" : "=f"(r) : "f"(s * 0.18033688011112042f));
    return r;
}

// Split 32 fp32 -> hi/lo bf16 into smem (8 float4 in, 32+32 bf16 out)
__device__ __forceinline__ void store_split32(bf16* dh, bf16* dl,
                                              const float4* g8) {
#pragma unroll
    for (int i = 0; i < 8; i++) {
        float4 av = g8[i];
        bf16 h0, l0, h1, l1, h2, l2, h3, l3;
        split2(av.x, h0, l0); split2(av.y, h1, l1);
        split2(av.z, h2, l2); split2(av.w, h3, l3);
        *(uint32_t*)(dh + i * 4)     = packbf2(h0, h1);
        *(uint32_t*)(dh + i * 4 + 2) = packbf2(h2, h3);
        *(uint32_t*)(dl + i * 4)     = packbf2(l0, l1);
        *(uint32_t*)(dl + i * 4 + 2) = packbf2(l2, l3);
    }
}

// LDSM per-thread byte offsets (validated).
__device__ __forceinline__ uint32_t a_ldsm_off(int lane, int ar0, int pitch) {
    return (uint32_t)(((ar0 + (lane & 15)) * pitch + ((lane >> 1) & 8)) * 2);
}
__device__ __forceinline__ uint32_t b_ldsm_off(int lane, int pitch) {
    return (uint32_t)((((lane & 7) + ((lane >> 1) & 8)) * pitch + (lane & 8)) * 2);
}
__device__ __forceinline__ uint32_t bt_ldsm_off(int lane, int pitch) {
    return (uint32_t)(((lane & 15) * pitch + ((lane >> 4) * 8)) * 2);
}

// ============================================================================
// Fused attention, single pass (validated R14) + folded exp.
// ============================================================================
__global__ __launch_bounds__(256, 2) void attn_fused_kernel(
    const bf16* __restrict__ qhi, const bf16* __restrict__ qlo,
    const bf16* __restrict__ khi, const bf16* __restrict__ klo,
    const bf16* __restrict__ vhi, const bf16* __restrict__ vlo,
    const unsigned int* __restrict__ m32,
    float* __restrict__ attn, float* __restrict__ ginv,
    bf16* __restrict__ ctxhi, bf16* __restrict__ ctxlo)
{
    extern __shared__ __align__(16) char smem[];
    bf16* sQh = (bf16*)smem;
    bf16* sQl = sQh + 128 * GP;
    bf16* sKh = sQl + 128 * GP;
    bf16* sKl = sKh + 128 * GP;
    bf16* sVh = sKl + 128 * GP;
    bf16* sVl = sVh + 128 * GP;
    float* sinv = (float*)(sVl + 128 * GP);

    int tid = threadIdx.x, lane = tid & 31, w = tid >> 5;
    int row0 = blockIdx.x * 128;
    int z = blockIdx.y, h = z / B_, b = z % B_;

    {
        int r = tid >> 1, half = tid & 1;
        size_t qo = ((size_t)(b * L_ + row0 + r) * E_) + h * DK_ + half * 32;
        const uint4* gqh = (const uint4*)(qhi + qo);
        const uint4* gql = (const uint4*)(qlo + qo);
        uint4* dqh = (uint4*)(sQh + r * GP + half * 32);
        uint4* dql = (uint4*)(sQl + r * GP + half * 32);
#pragma unroll
        for (int i = 0; i < 4; i++) { dqh[i] = gqh[i]; dql[i] = gql[i]; }
    }

    int lr0 = w * 16 + (lane >> 2);
    int r0g = row0 + lr0;

    uint32_t uQh = smem_u32(sQh), uQl = smem_u32(sQl);
    uint32_t uKh = smem_u32(sKh), uKl = smem_u32(sKl);
    uint32_t uVh = smem_u32(sVh), uVl = smem_u32(sVl);
    uint32_t aoff = a_ldsm_off(lane, w * 16, GP);
    uint32_t boffK = b_ldsm_off(lane, GP);
    uint32_t boffVt = bt_ldsm_off(lane, GP);

    const size_t mb = (size_t)b * L_ * L_;
    const unsigned int* M0 = m32 + ((mb + (size_t)r0g * L_) >> 5);
    const unsigned int* M1 = m32 + ((mb + (size_t)(r0g + 8) * L_) >> 5);
    float* Az = attn + (size_t)z * L_ * L_;

    float rs0 = 0.f, rs1 = 0.f;
    float accv[8][4];
#pragma unroll
    for (int nb = 0; nb < 8; nb++)
#pragma unroll
        for (int j = 0; j < 4; j++) accv[nb][j] = 0.f;

    for (int kt = 0; kt < 16; kt++) {
        int k0 = kt * 128;
        __syncthreads();
        {
            int r = tid >> 1, half = tid & 1;
            size_t ko = ((size_t)(b * L_ + k0 + r) * E_) + h * DK_ + half * 32;
            const uint4* gkh = (const uint4*)(khi + ko);
            const uint4* gkl = (const uint4*)(klo + ko);
            const uint4* gvh = (const uint4*)(vhi + ko);
            const uint4* gvl = (const uint4*)(vlo + ko);
            uint4* dkh = (uint4*)(sKh + r * GP + half * 32);
            uint4* dkl = (uint4*)(sKl + r * GP + half * 32);
            uint4* dvh = (uint4*)(sVh + r * GP + half * 32);
            uint4* dvl = (uint4*)(sVl + r * GP + half * 32);
#pragma unroll
            for (int i = 0; i < 4; i++) {
                dkh[i] = gkh[i]; dkl[i] = gkl[i];
                dvh[i] = gvh[i]; dvl[i] = gvl[i];
            }
        }
        __syncthreads();

        float acc[16][4];
#pragma unroll
        for (int nb = 0; nb < 16; nb++)
#pragma unroll
            for (int j = 0; j < 4; j++) acc[nb][j] = 0.f;
#pragma unroll
        for (int pass = 0; pass < 3; pass++) {
            uint32_t aB = ((pass == 2) ? uQl : uQh) + aoff;
            uint32_t bB = ((pass == 1) ? uKl : uKh) + boffK;
#pragma unroll
            for (int ks = 0; ks < 4; ks++) {
                uint32_t a0, a1, a2, a3;
                LDSM_X4(a0, a1, a2, a3, aB + ks * 32);
#pragma unroll
                for (int j = 0; j < 8; j++) {
                    uint32_t b0, b1, b2, b3;
                    LDSM_X4(b0, b1, b2, b3, bB + j * (16 * GP * 2) + ks * 32);
                    mma16816(acc[2 * j],     a0, a1, a2, a3, b0, b1);
                    mma16816(acc[2 * j + 1], a0, a1, a2, a3, b2, b3);
                }
            }
        }

        int wb = k0 >> 5;
        unsigned int mw0[4] = {M0[wb], M0[wb + 1], M0[wb + 2], M0[wb + 3]};
        unsigned int mw1[4] = {M1[wb], M1[wb + 1], M1[wb + 2], M1[wb + 3]};
#pragma unroll
        for (int nb = 0; nb < 16; nb++) {
            int cl = nb * 8 + (lane & 3) * 2;
            int cg = k0 + cl;
            unsigned int b0m = (mw0[cl >> 5] >> (cl & 31)) & 3u;
            unsigned int b1m = (mw1[cl >> 5] >> (cl & 31)) & 3u;
            float p00 = (b0m & 1u) ? 0.f : fexp8(acc[nb][0]);
            float p01 = (b0m & 2u) ? 0.f : fexp8(acc[nb][1]);
            float p10 = (b1m & 1u) ? 0.f : fexp8(acc[nb][2]);
            float p11 = (b1m & 2u) ? 0.f : fexp8(acc[nb][3]);
            __stcs((float2*)(Az + (size_t)r0g * L_ + cg), make_float2(p00, p01));
            __stcs((float2*)(Az + (size_t)(r0g + 8) * L_ + cg), make_float2(p10, p11));
            rs0 += p00 + p01;
            rs1 += p10 + p11;
            acc[nb][0] = p00; acc[nb][1] = p01;
            acc[nb][2] = p10; acc[nb][3] = p11;
        }

#pragma unroll
        for (int ks = 0; ks < 8; ks++) {
            int n0 = 2 * ks, n1 = n0 + 1;
            bf16 h00, l00, h01, l01, h10, l10, h11, l11;
            split2(acc[n0][0], h00, l00); split2(acc[n0][1], h01, l01);
            split2(acc[n0][2], h10, l10); split2(acc[n0][3], h11, l11);
            uint32_t ah0 = packbf2(h00, h01), al0 = packbf2(l00, l01);
            uint32_t ah1 = packbf2(h10, h11), al1 = packbf2(l10, l11);
            split2(acc[n1][0], h00, l00); split2(acc[n1][1], h01, l01);
            split2(acc[n1][2], h10, l10); split2(acc[n1][3], h11, l11);
            uint32_t ah2 = packbf2(h00, h01), al2 = packbf2(l00, l01);
            uint32_t ah3 = packbf2(h10, h11), al3 = packbf2(l10, l11);
            uint32_t kofs = (uint32_t)(ks * 16 * GP * 2);
#pragma unroll
            for (int j = 0; j < 4; j++) {
                uint32_t bh0, bh1, bh2, bh3, bl0, bl1, bl2, bl3;
                LDSM_X4_T(bh0, bh1, bh2, bh3, uVh + boffVt + kofs + j * 32);
                LDSM_X4_T(bl0, bl1, bl2, bl3, uVl + boffVt + kofs + j * 32);
                mma16816(accv[2 * j], ah0, ah1, ah2, ah3, bh0, bh1);
                mma16816(accv[2 * j], ah0, ah1, ah2, ah3, bl0, bl1);
                mma16816(accv[2 * j], al0, al1, al2, al3, bh0, bh1);
                mma16816(accv[2 * j + 1], ah0, ah1, ah2, ah3, bh2, bh3);
                mma16816(accv[2 * j + 1], ah0, ah1, ah2, ah3, bl2, bl3);
                mma16816(accv[2 * j + 1], al0, al1, al2, al3, bh2, bh3);
            }
        }
    }

    rs0 += __shfl_xor_sync(0xffffffffu, rs0, 1);
    rs0 += __shfl_xor_sync(0xffffffffu, rs0, 2);
    rs1 += __shfl_xor_sync(0xffffffffu, rs1, 1);
    rs1 += __shfl_xor_sync(0xffffffffu, rs1, 2);
    if ((lane & 3) == 0) {
        sinv[lr0] = 1.0f / rs0;
        sinv[lr0 + 8] = 1.0f / rs1;
    }
    __syncthreads();
    if (tid < 128) ginv[(size_t)z * L_ + row0 + tid] = sinv[tid];
    float inv0 = sinv[lr0], inv1 = sinv[lr0 + 8];

#pragma unroll
    for (int nb = 0; nb < 8; nb++) {
        int cg = nb * 8 + (lane & 3) * 2;
        size_t o0 = ((size_t)(b * L_ + r0g)) * E_ + h * DV_ + cg;
        size_t o1 = ((size_t)(b * L_ + r0g + 8)) * E_ + h * DV_ + cg;
        bf162 h2, l2;
        split2(accv[nb][0] * inv0, h2.x, l2.x);
        split2(accv[nb][1] * inv0, h2.y, l2.y);
        *(bf162*)(ctxhi + o0) = h2;
        *(bf162*)(ctxlo + o0) = l2;
        split2(accv[nb][2] * inv1, h2.x, l2.x);
        split2(accv[nb][3] * inv1, h2.y, l2.y);
        *(bf162*)(ctxhi + o1) = h2;
        *(bf162*)(ctxlo + o1) = l2;
    }
}
#define AF_SMEM_BYTES (6 * 128 * GP * 2 + 512)

// ============================================================================
// HMMA NT GEMM, fp32 inputs with inline hi/lo split: C = A @ B^T + bias
// ============================================================================
__device__ __forceinline__ void hmma_nt_f32_body(
    const float* __restrict__ A, const float* __restrict__ Bw,
    const float* __restrict__ bias,
    bf16* __restrict__ Chi, bf16* __restrict__ Clo,
    int K, int ldc, int row0, int col0)
{
    extern __shared__ __align__(16) char smem[];
    bf16* sAh = (bf16*)smem;
    bf16* sAl = sAh + 128 * GP;
    bf16* sBh = sAl + 128 * GP;
    bf16* sBl = sBh + 128 * GP;

    int tid = threadIdx.x, lane = tid & 31, w = tid >> 5;

    float acc[16][4];
#pragma unroll
    for (int nb = 0; nb < 16; nb++)
#pragma unroll
        for (int j = 0; j < 4; j++) acc[nb][j] = 0.f;

    int r = tid >> 1, half = tid & 1;
    const float* gA = A + (size_t)(row0 + r) * K + half * 32;
    const float* gB = Bw + (size_t)(col0 + r) * K + half * 32;
    bf16* dAh = sAh + r * GP + half * 32;
    bf16* dAl = sAl + r * GP + half * 32;
    bf16* dBh = sBh + r * GP + half * 32;
    bf16* dBl = sBl + r * GP + half * 32;

    uint32_t uAh = smem_u32(sAh), uAl = smem_u32(sAl);
    uint32_t uBh = smem_u32(sBh), uBl = smem_u32(sBl);
    uint32_t aoff = a_ldsm_off(lane, w * 16, GP);
    uint32_t boff = b_ldsm_off(lane, GP);

    for (int k0 = 0; k0 < K; k0 += 64) {
        __syncthreads();
        store_split32(dAh, dAl, (const float4*)(gA + k0));
        store_split32(dBh, dBl, (const float4*)(gB + k0));
        __syncthreads();
#pragma unroll
        for (int pass = 0; pass < 3; pass++) {
            uint32_t aB = ((pass == 2) ? uAl : uAh) + aoff;
            uint32_t bB = ((pass == 1) ? uBl : uBh) + boff;
#pragma unroll
            for (int ks = 0; ks < 4; ks++) {
                uint32_t a0, a1, a2, a3;
                LDSM_X4(a0, a1, a2, a3, aB + ks * 32);
#pragma unroll
                for (int j = 0; j < 8; j++) {
                    uint32_t b0, b1, b2, b3;
                    LDSM_X4(b0, b1, b2, b3, bB + j * (16 * GP * 2) + ks * 32);
                    mma16816(acc[2 * j],     a0, a1, a2, a3, b0, b1);
                    mma16816(acc[2 * j + 1], a0, a1, a2, a3, b2, b3);
                }
            }
        }
    }

    int r0g = row0 + w * 16 + (lane >> 2);
#pragma unroll
    for (int nb = 0; nb < 16; nb++) {
        int cg = col0 + nb * 8 + (lane & 3) * 2;
        float f00 = acc[nb][0] + bias[cg];
        float f01 = acc[nb][1] + bias[cg + 1];
        float f10 = acc[nb][2] + bias[cg];
        float f11 = acc[nb][3] + bias[cg + 1];
        bf162 h2, l2;
        split2(f00, h2.x, l2.x); split2(f01, h2.y, l2.y);
        *(bf162*)(Chi + (size_t)r0g * ldc + cg) = h2;
        *(bf162*)(Clo + (size_t)r0g * ldc + cg) = l2;
        split2(f10, h2.x, l2.x); split2(f11, h2.y, l2.y);
        *(bf162*)(Chi + (size_t)(r0g + 8) * ldc + cg) = h2;
        *(bf162*)(Clo + (size_t)(r0g + 8) * ldc + cg) = l2;
    }
}

// A = bf16 hi/lo (ctx), B = fp32 (Wfc), output fp32
__device__ __forceinline__ void hmma_nt_bf_f32_body(
    const bf16* __restrict__ Ahi, const bf16* __restrict__ Alo,
    const float* __restrict__ Bw, const float* __restrict__ bias,
    float* __restrict__ Cf, int K, int ldc, int row0, int col0)
{
    extern __shared__ __align__(16) char smem[];
    bf16* sAh = (bf16*)smem;
    bf16* sAl = sAh + 128 * GP;
    bf16* sBh = sAl + 128 * GP;
    bf16* sBl = sBh + 128 * GP;

    int tid = threadIdx.x, lane = tid & 31, w = tid >> 5;

    float acc[16][4];
#pragma unroll
    for (int nb = 0; nb < 16; nb++)
#pragma unroll
        for (int j = 0; j < 4; j++) acc[nb][j] = 0.f;

    int r = tid >> 1, half = tid & 1;
    const bf16* gAh = Ahi + (size_t)(row0 + r) * K + half * 32;
    const bf16* gAl = Alo + (size_t)(row0 + r) * K + half * 32;
    const float* gB = Bw + (size_t)(col0 + r) * K + half * 32;
    bf16* dAh = sAh + r * GP + half * 32;
    bf16* dAl = sAl + r * GP + half * 32;
    bf16* dBh = sBh + r * GP + half * 32;
    bf16* dBl = sBl + r * GP + half * 32;

    uint32_t uAh = smem_u32(sAh), uAl = smem_u32(sAl);
    uint32_t uBh = smem_u32(sBh), uBl = smem_u32(sBl);
    uint32_t aoff = a_ldsm_off(lane, w * 16, GP);
    uint32_t boff = b_ldsm_off(lane, GP);

    for (int k0 = 0; k0 < K; k0 += 64) {
        __syncthreads();
        {
            const uint4* a4h = (const uint4*)(gAh + k0);
            const uint4* a4l = (const uint4*)(gAl + k0);
#pragma unroll
            for (int i = 0; i < 4; i++) {
                ((uint4*)dAh)[i] = a4h[i];
                ((uint4*)dAl)[i] = a4l[i];
            }
        }
        store_split32(dBh, dBl, (const float4*)(gB + k0));
        __syncthreads();
#pragma unroll
        for (int pass = 0; pass < 3; pass++) {
            uint32_t aB = ((pass == 2) ? uAl : uAh) + aoff;
            uint32_t bB = ((pass == 1) ? uBl : uBh) + boff;
#pragma unroll
            for (int ks = 0; ks < 4; ks++) {
                uint32_t a0, a1, a2, a3;
                LDSM_X4(a0, a1, a2, a3, aB + ks * 32);
#pragma unroll
                for (int j = 0; j < 8; j++) {
                    uint32_t b0, b1, b2, b3;
                    LDSM_X4(b0, b1, b2, b3, bB + j * (16 * GP * 2) + ks * 32);
                    mma16816(acc[2 * j],     a0, a1, a2, a3, b0, b1);
                    mma16816(acc[2 * j + 1], a0, a1, a2, a3, b2, b3);
                }
            }
        }
    }

    int r0g = row0 + w * 16 + (lane >> 2);
#pragma unroll
    for (int nb = 0; nb < 16; nb++) {
        int cg = col0 + nb * 8 + (lane & 3) * 2;
        float f00 = acc[nb][0] + bias[cg];
        float f01 = acc[nb][1] + bias[cg + 1];
        float f10 = acc[nb][2] + bias[cg];
        float f11 = acc[nb][3] + bias[cg + 1];
        *(float2*)(Cf + (size_t)r0g * ldc + cg) = make_float2(f00, f01);
        *(float2*)(Cf + (size_t)(r0g + 8) * ldc + cg) = make_float2(f10, f11);
    }
}
#define HMMA_SMEM (4 * 128 * GP * 2)

// ============================================================================
// qkv (z=0..2, fp32 inline split) + mask bit-pack (z=3) in ONE launch
// ============================================================================
__global__ __launch_bounds__(256, 2) void qkv_mask_kernel(
    const float* __restrict__ q, const float* __restrict__ k,
    const float* __restrict__ v,
    const float* __restrict__ Wq, const float* __restrict__ Wk,
    const float* __restrict__ Wv,
    const float* __restrict__ bq, const float* __restrict__ bk,
    const float* __restrict__ bv,
    bf16* __restrict__ qhi, bf16* __restrict__ qlo,
    bf16* __restrict__ khi, bf16* __restrict__ klo,
    bf16* __restrict__ vhi, bf16* __restrict__ vlo,
    const void* __restrict__ mask, unsigned int* __restrict__ m32)
{
    int zz = blockIdx.z;
    if (zz < 3) {
        const float* A = (zz == 0) ? q : (zz == 1) ? k : v;
        const float* W = (zz == 0) ? Wq : (zz == 1) ? Wk : Wv;
        const float* bias = (zz == 0) ? bq : (zz == 1) ? bk : bv;
        bf16* Chi = (zz == 0) ? qhi : (zz == 1) ? khi : vhi;
        bf16* Clo = (zz == 0) ? qlo : (zz == 1) ? klo : vlo;
        hmma_nt_f32_body(A, W, bias, Chi, Clo, E_, E_,
                         blockIdx.y * 128, blockIdx.x * 128);
        return;
    }
    // ---- mask pack: 256 blocks x 2048 words = 524288 words total ----
    __shared__ int s_byte;
    int tid = threadIdx.x;
    if (tid == 0) {
        const unsigned int* mi = (const unsigned int*)mask;
        int bm = 0;
#pragma unroll 8
        for (int i = 0; i < 64; i++) if (mi[i] > 1u) bm = 1;
        s_byte = bm;
    }
    __syncthreads();
    int blk = blockIdx.y * 4 + blockIdx.x;   // 0..255
    int sb = s_byte;
#pragma unroll 2
    for (int it = 0; it < 8; it++) {
        size_t widx = (size_t)blk * 2048 + it * 256 + tid;
        unsigned int wv = 0;
        if (sb) {
            const unsigned int* p = (const unsigned int*)mask + widx * 8;
#pragma unroll
            for (int j = 0; j < 8; j++) {
                unsigned int vv = p[j];
                if (vv & 0x000000FFu) wv |= 1u << (j * 4 + 0);
                if (vv & 0x0000FF00u) wv |= 1u << (j * 4 + 1);
                if (vv & 0x00FF0000u) wv |= 1u << (j * 4 + 2);
                if (vv & 0xFF000000u) wv |= 1u << (j * 4 + 3);
            }
        } else {
            const int4* p = (const int4*)mask + widx * 8;
#pragma unroll
            for (int j = 0; j < 8; j++) {
                int4 vv = p[j];
                if (vv.x) wv |= 1u << (j * 4 + 0);
                if (vv.y) wv |= 1u << (j * 4 + 1);
                if (vv.z) wv |= 1u << (j * 4 + 2);
                if (vv.w) wv |= 1u << (j * 4 + 3);
            }
        }
        m32[widx] = wv;
    }
}

// ============================================================================
// finish1: fc GEMM (x < 256) + attn normalization sweep half 1
// finish2: LayerNorm (x < 8192) + sweep half 2
// ============================================================================
#define SWEEP_BLOCKS 1024
#define SWEEP_F4     16384

__device__ __forceinline__ void sweep_chunk(float* __restrict__ attn,
                                            const float* __restrict__ ginv,
                                            size_t base_f4)
{
    float4* A4 = (float4*)attn;
    int tid = threadIdx.x;
#pragma unroll 4
    for (int it = 0; it < SWEEP_F4 / 256; it++) {
        size_t f = base_f4 + (size_t)it * 256 + tid;
        float inv = __ldg(ginv + (f >> 9));
        float4 vv = __ldcs(A4 + f);
        vv.x *= inv; vv.y *= inv; vv.z *= inv; vv.w *= inv;
        __stcs(A4 + f, vv);
    }
}

__global__ __launch_bounds__(256, 2) void finish1_kernel(
    const bf16* __restrict__ ctxhi, const bf16* __restrict__ ctxlo,
    const float* __restrict__ Wfc, const float* __restrict__ bfc,
    float* __restrict__ fc,
    float* __restrict__ attn, const float* __restrict__ ginv)
{
    if (blockIdx.x < 256) {
        hmma_nt_bf_f32_body(ctxhi, ctxlo, Wfc, bfc, fc, E_, E_,
                            (blockIdx.x >> 2) * 128, (blockIdx.x & 3) * 128);
    } else {
        sweep_chunk(attn, ginv, (size_t)(blockIdx.x - 256) * SWEEP_F4);
    }
}

__global__ void finish2_kernel(
    const float* __restrict__ fc, const float* __restrict__ resid,
    const float* __restrict__ gamma, const float* __restrict__ beta,
    float* __restrict__ out,
    float* __restrict__ attn, const float* __restrict__ ginv)
{
    if (blockIdx.x >= 8192) {
        sweep_chunk(attn, ginv,
                    (size_t)SWEEP_BLOCKS * SWEEP_F4 +
                    (size_t)(blockIdx.x - 8192) * SWEEP_F4);
        return;
    }
    size_t base = (size_t)blockIdx.x * E_;
    int tid = threadIdx.x;
    float x0 = fc[base + tid] + resid[base + tid];
    float x1 = fc[base + tid + 256] + resid[base + tid + 256];
    float s = x0 + x1;
    float ss = x0 * x0 + x1 * x1;

    __shared__ float rs[8], rss[8];
#pragma unroll
    for (int o = 16; o; o >>= 1) {
        s  += __shfl_xor_sync(0xffffffffu, s, o);
        ss += __shfl_xor_sync(0xffffffffu, ss, o);
    }
    if ((tid & 31) == 0) { rs[tid >> 5] = s; rss[tid >> 5] = ss; }
    __syncthreads();
    s = 0.f; ss = 0.f;
#pragma unroll
    for (int i = 0; i < 8; i++) { s += rs[i]; ss += rss[i]; }

    float mu = s * (1.0f / E_);
    float var = ss * (1.0f / E_) - mu * mu;
    float rstd = rsqrtf(var + 1e-5f);
    out[base + tid]       = (x0 - mu) * rstd * gamma[tid] + beta[tid];
    out[base + tid + 256] = (x1 - mu) * rstd * gamma[tid + 256] + beta[tid + 256];
}

// ============================================================================
extern "C" void kernel_launch(void* const* d_in, const int* in_sizes, int n_in,
                              void* d_out, int out_size)
{
    const float* q    = (const float*)d_in[0];
    const float* k    = (const float*)d_in[1];
    const float* v    = (const float*)d_in[2];
    const void*  mask = (const void*)d_in[3];
    const float* Wq   = (const float*)d_in[4];
    const float* bq   = (const float*)d_in[5];
    const float* Wk   = (const float*)d_in[6];
    const float* bk   = (const float*)d_in[7];
    const float* Wv   = (const float*)d_in[8];
    const float* bv   = (const float*)d_in[9];
    const float* Wfc  = (const float*)d_in[10];
    const float* bfc  = (const float*)d_in[11];
    const float* gamma = (const float*)d_in[12];
    const float* beta  = (const float*)d_in[13];

    float* out  = (float*)d_out;
    float* attn = out + (size_t)B_ * L_ * E_;

    float *fc, *ginv;
    bf16 *qhi, *qlo, *khi, *klo, *vhi, *vlo, *ctxhi, *ctxlo;
    unsigned int* m32;
    cudaGetSymbolAddress((void**)&fc,    g_fc);
    cudaGetSymbolAddress((void**)&ginv,  g_inv);
    cudaGetSymbolAddress((void**)&qhi,   g_qhi);
    cudaGetSymbolAddress((void**)&qlo,   g_qlo);
    cudaGetSymbolAddress((void**)&khi,   g_khi);
    cudaGetSymbolAddress((void**)&klo,   g_klo);
    cudaGetSymbolAddress((void**)&vhi,   g_vhi);
    cudaGetSymbolAddress((void**)&vlo,   g_vlo);
    cudaGetSymbolAddress((void**)&ctxhi, g_ctxhi);
    cudaGetSymbolAddress((void**)&ctxlo, g_ctxlo);
    cudaGetSymbolAddress((void**)&m32,   g_mask32);

    cudaFuncSetAttribute(attn_fused_kernel,
                         cudaFuncAttributeMaxDynamicSharedMemorySize, AF_SMEM_BYTES);
    cudaFuncSetAttribute(qkv_mask_kernel,
                         cudaFuncAttributeMaxDynamicSharedMemorySize, HMMA_SMEM);
    cudaFuncSetAttribute(finish1_kernel,
                         cudaFuncAttributeMaxDynamicSharedMemorySize, HMMA_SMEM);

    // qkv (tensor, fp32 inline split) + mask pack (memory) overlapped
    dim3 gqm(E_ / 128, (B_ * L_) / 128, 4);          // (4, 64, 4)
    qkv_mask_kernel<<<gqm, 256, HMMA_SMEM>>>(q, k, v, Wq, Wk, Wv, bq, bk, bv,
                                             qhi, qlo, khi, klo, vhi, vlo,
                                             mask, m32);

    // fused single-pass attention
    dim3 gaf(L_ / 128, H_ * B_);                     // (16, 32)
    attn_fused_kernel<<<gaf, 256, AF_SMEM_BYTES>>>(
        qhi, qlo, khi, klo, vhi, vlo, m32, attn, ginv, ctxhi, ctxlo);

    // fc (tensor, fp32 W inline split) + sweep half1 (memory) overlapped
    finish1_kernel<<<256 + SWEEP_BLOCKS, 256, HMMA_SMEM>>>(
        ctxhi, ctxlo, Wfc, bfc, fc, attn, ginv);

    // ln (memory) + sweep half2 (memory)
    finish2_kernel<<<8192 + SWEEP_BLOCKS, 256>>>(
        fc, q, gamma, beta, out, attn, ginv);
}